// round 16
// baseline (speedup 1.0000x reference)
#include <cuda_runtime.h>
#include <math.h>

#define NB 4
#define SQ 1024
#define DM 1024
#define NH 16
#define DKH 64
#define NKV (NB * NH * SQ * DKH)
#define NELEM 67108864u

// ---------------- scratch ----------------------------------------------------
__device__ unsigned g_bern[NELEM / 32];
__device__ float g_vsuf[64 * 32 * 64];
// fragment-packed operands: float4 {hi[r], hi[r+4], lo[r], lo[r+4]}, r=kg*8+tg
__device__ float g_xp[8388608];    // x packed:  [pr=512][m=4096] float4
__device__ float g_wp[8388608];    // Wq|Wk|Wv|Wo packed: per W [pr=512][n=1024] float4
__device__ float g_aop[8388608];   // attn out packed: [pr=512][m=4096] float4
// attention operands (pre-split hi/lo, [b,h,s,d])
__device__ float g_qhi[NKV], g_qlo[NKV];
__device__ float g_khi[NKV], g_klo[NKV];
__device__ float g_vhi[NKV], g_vlo[NKV];

// ---------------- threefry2x32 (JAX partitionable, key=(0,42)) --------------
__device__ __forceinline__ unsigned rotl32(unsigned x, int r) {
    return __funnelshift_l(x, x, r);
}

__device__ __forceinline__ unsigned bern_bit(unsigned e) {
    unsigned x0 = 0u;
    unsigned x1 = e;
    const unsigned ks1 = 42u;
    const unsigned ks2 = 0x1BD11BDAu ^ 42u;
    x1 += ks1;
#define TF_RND(r) { x0 += x1; x1 = rotl32(x1, (r)); x1 ^= x0; }
    TF_RND(13) TF_RND(15) TF_RND(26) TF_RND(6)
    x0 += ks1; x1 += ks2 + 1u;
    TF_RND(17) TF_RND(29) TF_RND(16) TF_RND(24)
    x0 += ks2; x1 += 0u + 2u;
    TF_RND(13) TF_RND(15) TF_RND(26) TF_RND(6)
    x0 += 0u; x1 += ks1 + 3u;
    TF_RND(17) TF_RND(29) TF_RND(16) TF_RND(24)
    x0 += ks1; x1 += ks2 + 4u;
    TF_RND(13) TF_RND(15) TF_RND(26) TF_RND(6)
    x0 += ks2; x1 += 0u + 5u;
#undef TF_RND
    unsigned bits = x0 ^ x1;
    return ((bits >> 9) < 2516583u) ? 1u : 0u;   // uniform(bits) < 0.3f
}

__device__ void bern_chunk(int blk, int tid) {
    unsigned t = (unsigned)blk * 256u + (unsigned)tid;
    for (unsigned i = 0; i < 1024u; i++) {
        unsigned e = t + i * 65536u;
        unsigned qr = (e >> 10) & 1023u;
        unsigned kg0 = e & 992u;
        if (kg0 > qr) continue;           // dead bits (causal overwrite)
        unsigned keep = bern_bit(e);
        unsigned w = __ballot_sync(0xffffffffu, keep != 0u);
        if ((tid & 31) == 0) g_bern[e >> 5] = w;
    }
}

// ---------------- tf32 helpers ----------------------------------------------
__device__ __forceinline__ unsigned f2tf(float x) {
    unsigned r;
    asm("cvt.rna.tf32.f32 %0, %1;" : "=r"(r) : "f"(x));
    return r;
}
__device__ __forceinline__ float tf_hi(float x) { return __uint_as_float(f2tf(x)); }

__device__ __forceinline__ void mma_tf32(float c[4], const unsigned a[4], const unsigned b[2]) {
    asm volatile(
        "mma.sync.aligned.m16n8k8.row.col.f32.tf32.tf32.f32 "
        "{%0,%1,%2,%3}, {%4,%5,%6,%7}, {%8,%9}, {%0,%1,%2,%3};"
        : "+f"(c[0]), "+f"(c[1]), "+f"(c[2]), "+f"(c[3])
        : "r"(a[0]), "r"(a[1]), "r"(a[2]), "r"(a[3]), "r"(b[0]), "r"(b[1]));
}

__device__ __forceinline__ void cp16(void* dst_smem, const void* src) {
    unsigned d = (unsigned)__cvta_generic_to_shared(dst_smem);
    asm volatile("cp.async.cg.shared.global [%0], [%1], 16;" :: "r"(d), "l"(src) : "memory");
}

// ---------------- prep: fragment-pack x and W --------------------------------
__global__ void __launch_bounds__(256) split_kernel(
    const float* __restrict__ x,
    const float* __restrict__ Wq, const float* __restrict__ Wk,
    const float* __restrict__ Wv, const float* __restrict__ Wo)
{
    unsigned idx = blockIdx.x * 256u + threadIdx.x;
    if (idx < 4194304u) {
        // x: [m=4096][k=1024]; pairs along k via shfl
        unsigned m = idx >> 10, k = idx & 1023u;
        float v = x[idx];
        float hv = tf_hi(v);
        float lv = tf_hi(v - hv);
        float hv4 = __shfl_down_sync(0xffffffffu, hv, 4);
        float lv4 = __shfl_down_sync(0xffffffffu, lv, 4);
        if ((k & 7u) < 4u) {
            unsigned pr = ((k >> 3) << 2) | (k & 3u);
            ((float4*)g_xp)[(size_t)pr * 4096 + m] = make_float4(hv, hv4, lv, lv4);
        }
    } else {
        // W: [k=1024][n=1024]; pairs are rows r, r+4 (both reads coalesced)
        unsigned j = idx - 4194304u;      // 0 .. 2M-1
        unsigned w = j >> 19;             // 0..3
        unsigned rem = j & 524287u;       // pr*1024 + n
        unsigned pr = rem >> 10;
        unsigned n = rem & 1023u;
        unsigned r = (pr >> 2) * 8u + (pr & 3u);
        const float* W = (w == 0) ? Wq : (w == 1) ? Wk : (w == 2) ? Wv : Wo;
        float v0 = W[r * 1024 + n];
        float v1 = W[(r + 4) * 1024 + n];
        float h0 = tf_hi(v0), l0 = tf_hi(v0 - h0);
        float h1 = tf_hi(v1), l1 = tf_hi(v1 - h1);
        ((float4*)g_wp)[((size_t)w << 19) + rem] = make_float4(h0, h1, l0, l1);
    }
}

// ---------------- tf32x3 GEMM on packed operands -----------------------------
// BM=128, BN=128, BK=16; 8 warps 4(M)x2(N), warp tile 32x64; 3-stage cp.async.
// Fragment loads are single LDS.128 (12 per k-halfstep vs 48 scalar before).
#define FPAD 130                       // float4 row stride (FPAD%8==2: conflict-free)
#define STG4 (8 * FPAD)                // 1040 float4 per operand stage
#define STAGE_F4 (2 * STG4)            // 2080 float4
#define NSTAGE 3
#define SMEM_GEMM_BYTES (STAGE_F4 * NSTAGE * 16)   // 99840

__device__ __forceinline__ void issue_stage(
    const float4* __restrict__ Ap, const float4* __restrict__ Bp,
    int m0, int n0, int kt, float4* stage, int tid)
{
    float4* sA = stage;
    float4* sB = stage + STG4;
    int kg0 = (kt >> 3) << 2;          // pair-row base
#pragma unroll
    for (int i = 0; i < 4; i++) {
        int c = tid + i * 256;          // 0..1023
        int rr = c >> 7;                // 0..7
        int mm = c & 127;
        int gr = kg0 + rr;
        cp16(sA + rr * FPAD + mm, Ap + (size_t)gr * 4096 + m0 + mm);
        cp16(sB + rr * FPAD + mm, Bp + (size_t)gr * 1024 + n0 + mm);
    }
    asm volatile("cp.async.commit_group;" ::: "memory");
}

// SCATTER=1: write q/k/v hi/lo float2 pairs in [b,h,s,d]; SCATTER=0: row-major.
template <int SCATTER>
__device__ __forceinline__ void gemm_body(
    const float4* __restrict__ Ap, const float4* __restrict__ Bp,
    const float* __restrict__ bias,
    float* __restrict__ outhi, float* __restrict__ outlo)
{
    extern __shared__ float4 smf4[];
    int tid = threadIdx.x;
    int lane = tid & 31, warp = tid >> 5;
    int wm = warp & 3, wn = warp >> 2;
    int g = lane >> 2, tg = lane & 3;
    int m0 = blockIdx.y * 128, n0 = blockIdx.x * 128;

    float c[2][8][4];
#pragma unroll
    for (int mt = 0; mt < 2; mt++)
#pragma unroll
        for (int nt = 0; nt < 8; nt++)
#pragma unroll
            for (int i = 0; i < 4; i++) c[mt][nt][i] = 0.f;

    issue_stage(Ap, Bp, m0, n0, 0, smf4, tid);
    issue_stage(Ap, Bp, m0, n0, 16, smf4 + STAGE_F4, tid);

    int buf = 0;
    for (int it = 0; it < 64; it++) {
        if (it < 62) { asm volatile("cp.async.wait_group 1;" ::: "memory"); }
        else         { asm volatile("cp.async.wait_group 0;" ::: "memory"); }
        __syncthreads();

        if (it + 2 < 64) {
            int nbuf = buf + 2; if (nbuf >= NSTAGE) nbuf -= NSTAGE;
            issue_stage(Ap, Bp, m0, n0, (it + 2) * 16, smf4 + nbuf * STAGE_F4, tid);
        }

        const float4* sA = smf4 + buf * STAGE_F4;
        const float4* sB = sA + STG4;

#pragma unroll
        for (int k8x = 0; k8x < 2; k8x++) {
            int rowb = (k8x * 4 + tg) * FPAD;
            unsigned ah[2][4], al[2][4];
#pragma unroll
            for (int mt = 0; mt < 2; mt++) {
                int mb = wm * 32 + mt * 16;
                float4 L1 = sA[rowb + mb + g];
                float4 L2 = sA[rowb + mb + g + 8];
                ah[mt][0] = __float_as_uint(L1.x); ah[mt][1] = __float_as_uint(L2.x);
                ah[mt][2] = __float_as_uint(L1.y); ah[mt][3] = __float_as_uint(L2.y);
                al[mt][0] = __float_as_uint(L1.z); al[mt][1] = __float_as_uint(L2.z);
                al[mt][2] = __float_as_uint(L1.w); al[mt][3] = __float_as_uint(L2.w);
            }
#pragma unroll
            for (int nt = 0; nt < 8; nt++) {
                int nb = wn * 64 + nt * 8;
                float4 Bv = sB[rowb + nb + g];
                unsigned bh[2], bl[2];
                bh[0] = __float_as_uint(Bv.x); bh[1] = __float_as_uint(Bv.y);
                bl[0] = __float_as_uint(Bv.z); bl[1] = __float_as_uint(Bv.w);
#pragma unroll
                for (int mt = 0; mt < 2; mt++) {
                    mma_tf32(c[mt][nt], ah[mt], bh);
                    mma_tf32(c[mt][nt], ah[mt], bl);
                    mma_tf32(c[mt][nt], al[mt], bh);
                }
            }
        }
        buf++; if (buf >= NSTAGE) buf = 0;
    }

#pragma unroll
    for (int mt = 0; mt < 2; mt++)
#pragma unroll
        for (int nt = 0; nt < 8; nt++)
#pragma unroll
            for (int half = 0; half < 2; half++) {
                int row = m0 + wm * 32 + mt * 16 + g + half * 8;
                int col0 = n0 + wn * 64 + nt * 8 + tg * 2;
                float v0 = fmaxf(c[mt][nt][half * 2 + 0] + bias[col0], 0.f);
                float v1 = fmaxf(c[mt][nt][half * 2 + 1] + bias[col0 + 1], 0.f);
                if (SCATTER) {
                    int b = row >> 10, s = row & 1023;
                    int h = col0 >> 6, d = col0 & 63;
                    size_t idx = (((size_t)(b * NH + h)) * SQ + s) * DKH + d;
                    float h0 = tf_hi(v0);
                    float h1 = tf_hi(v1);
                    *(float2*)(outhi + idx) = make_float2(h0, h1);
                    *(float2*)(outlo + idx) = make_float2(tf_hi(v0 - h0), tf_hi(v1 - h1));
                } else {
                    *(float2*)(outhi + (size_t)row * 1024 + col0) = make_float2(v0, v1);
                }
            }
}

// z = 0/1/2: q/k/v projections. z = 3: bernoulli slice.
__global__ void __launch_bounds__(256, 2) qkv_gemm_kernel(
    const float* __restrict__ bq, const float* __restrict__ bk,
    const float* __restrict__ bv)
{
    if (blockIdx.z == 3) {
        bern_chunk(blockIdx.y * 8 + blockIdx.x, threadIdx.x);
        return;
    }
    int proj = blockIdx.z;
    const float* bias = (proj == 0) ? bq : (proj == 1) ? bk : bv;
    float* ohi = (proj == 0) ? g_qhi : (proj == 1) ? g_khi : g_vhi;
    float* olo = (proj == 0) ? g_qlo : (proj == 1) ? g_klo : g_vlo;
    gemm_body<1>((const float4*)g_xp,
                 (const float4*)g_wp + ((size_t)proj << 19),
                 bias, ohi, olo);
}

__global__ void __launch_bounds__(256, 2) out_gemm_kernel(
    const float* __restrict__ bias, float* __restrict__ out)
{
    gemm_body<0>((const float4*)g_aop,
                 (const float4*)g_wp + ((size_t)3 << 19),
                 bias, out, (float*)0);
}

// ---------------- V suffix sums (from hi+lo; error ~2^-22, negligible) -------
__global__ void __launch_bounds__(1024) vsuf_kernel() {
    int bh = blockIdx.x;
    __shared__ float part[32][64];
    int d = threadIdx.x & 63;
    int jj = threadIdx.x >> 6;
#pragma unroll
    for (int p = 0; p < 2; p++) {
        int j = p * 16 + jj;
        size_t base = ((size_t)bh * 1024 + j * 32) * 64 + d;
        float sum = 0.f;
#pragma unroll
        for (int s = 0; s < 32; s++)
            sum += g_vhi[base + s * 64] + g_vlo[base + s * 64];
        part[j][d] = sum;
    }
    __syncthreads();
    if (threadIdx.x < 64) {
        float run = 0.f;
        for (int j = 31; j >= 0; j--) {
            run += part[j][threadIdx.x];
            g_vsuf[((size_t)bh * 32 + j) * 64 + threadIdx.x] = run;
        }
    }
}

// ---------------- MMA flash attention: pre-split + cp.async double buffer ----
#define KS_W 76
#define VS_W 72
#define PS_W 36
#define PT_W 36
#define KOFF (32 * KS_W)
#define VOFF (32 * VS_W)
#define PSOFF (2 * KOFF + 2 * VOFF)
#define ATT_STAGE (PSOFF + 128 * PS_W)
#define SMEM_ATTN_FLOATS (2 * ATT_STAGE + 8 * 16 * PT_W + 32)
#define SMEM_ATTN_BYTES (SMEM_ATTN_FLOATS * 4)   // 131200

__device__ __forceinline__ void attn_issue(
    float* st, size_t kvbase, const float* __restrict__ pos,
    size_t posbase, int kb, int tid)
{
    float* Kh = st;
    float* Kl = st + KOFF;
    float* Vh = st + 2 * KOFF;
    float* Vl = st + 2 * KOFF + VOFF;
    float* ps = st + PSOFF;
#pragma unroll
    for (int i = 0; i < 2; i++) {
        int c = tid + i * 256;
        int key = c >> 4, d4 = (c & 15) * 4;
        size_t go = kvbase + key * 64 + d4;
        cp16(Kh + key * KS_W + d4, g_khi + go);
        cp16(Kl + key * KS_W + d4, g_klo + go);
        cp16(Vh + key * VS_W + d4, g_vhi + go);
        cp16(Vl + key * VS_W + d4, g_vlo + go);
    }
#pragma unroll
    for (int i = 0; i < 4; i++) {
        int c = tid + i * 256;
        int r = c >> 3, c4 = (c & 7) * 4;
        cp16(ps + r * PS_W + c4, pos + posbase + (size_t)r * SQ + kb + c4);
    }
    asm volatile("cp.async.commit_group;" ::: "memory");
}

__global__ void __launch_bounds__(256) attn_kernel(
    const float* __restrict__ pos, const int* __restrict__ mask)
{
    extern __shared__ float sm[];
    float* PtAll = sm + 2 * ATT_STAGE;
    unsigned* msk = (unsigned*)(PtAll + 8 * 16 * PT_W);   // [32] packed pad-mask

    int qb = (int)gridDim.x - 1 - (int)blockIdx.x;   // heavy blocks first
    int h = blockIdx.y, b = blockIdx.z;
    int tid = threadIdx.x;
    int lane = tid & 31, warp = tid >> 5;
    int g = lane >> 2, tg = lane & 3;
    float* Pt = PtAll + warp * 16 * PT_W;

    int qr0 = qb * 128 + warp * 16;
    int qrow_g = qr0 + g;
    int qrow_h = qr0 + g + 8;
    size_t bh = (size_t)(b * NH + h);
    size_t posbase = ((size_t)b * SQ + qb * 128) * SQ;

    // Pack the key-padding mask once per block: 32 words, 4 per warp.
#pragma unroll
    for (int j = 0; j < 4; j++) {
        int w = warp * 4 + j;
        unsigned bit = (mask[b * SQ + w * 32 + lane] != 0) ? 1u : 0u;
        unsigned word = __ballot_sync(0xffffffffu, bit != 0u);
        if (lane == 0) msk[w] = word;
    }

    // Q fragments: pre-split, straight into registers
    unsigned qa_hi[8][4], qa_lo[8][4];
    {
        const float* qh = g_qhi + (bh * SQ + qr0) * DKH;
        const float* ql = g_qlo + (bh * SQ + qr0) * DKH;
#pragma unroll
        for (int ks = 0; ks < 8; ks++) {
            qa_hi[ks][0] = __float_as_uint(qh[g * 64 + ks * 8 + tg]);
            qa_hi[ks][1] = __float_as_uint(qh[(g + 8) * 64 + ks * 8 + tg]);
            qa_hi[ks][2] = __float_as_uint(qh[g * 64 + ks * 8 + tg + 4]);
            qa_hi[ks][3] = __float_as_uint(qh[(g + 8) * 64 + ks * 8 + tg + 4]);
            qa_lo[ks][0] = __float_as_uint(ql[g * 64 + ks * 8 + tg]);
            qa_lo[ks][1] = __float_as_uint(ql[(g + 8) * 64 + ks * 8 + tg]);
            qa_lo[ks][2] = __float_as_uint(ql[g * 64 + ks * 8 + tg + 4]);
            qa_lo[ks][3] = __float_as_uint(ql[(g + 8) * 64 + ks * 8 + tg + 4]);
        }
    }

    float o[8][4];
#pragma unroll
    for (int nt = 0; nt < 8; nt++)
#pragma unroll
        for (int i = 0; i < 4; i++) o[nt][i] = 0.f;
    float m_g = -INFINITY, m_h = -INFINITY, l_g = 0.f, l_h = 0.f;

    int kb_end = (qb + 1) * 128;
    int qrow_base = warp * 16;

    attn_issue(sm, (bh * SQ + 0) * DKH, pos, posbase, 0, tid);

    int sbuf = 0;
    for (int kb = 0; kb < kb_end; kb += 32) {
        asm volatile("cp.async.wait_group 0;" ::: "memory");
        __syncthreads();
        if (kb + 32 < kb_end)
            attn_issue(sm + (sbuf ^ 1) * ATT_STAGE,
                       (bh * SQ + kb + 32) * DKH, pos, posbase, kb + 32, tid);

        const float* st = sm + sbuf * ATT_STAGE;
        const float* Ks_hi = st;
        const float* Ks_lo = st + KOFF;
        const float* Vs_hi = st + 2 * KOFF;
        const float* Vs_lo = st + 2 * KOFF + VOFF;
        const float* ps    = st + PSOFF;

        if (kb <= qr0) {
            float sc[4][4];
#pragma unroll
            for (int nt = 0; nt < 4; nt++)
#pragma unroll
                for (int i = 0; i < 4; i++) sc[nt][i] = 0.f;
#pragma unroll
            for (int ks = 0; ks < 8; ks++) {
#pragma unroll
                for (int nt = 0; nt < 4; nt++) {
                    unsigned bhh[2], bll[2];
                    bhh[0] = __float_as_uint(Ks_hi[(nt * 8 + g) * KS_W + ks * 8 + tg]);
                    bhh[1] = __float_as_uint(Ks_hi[(nt * 8 + g) * KS_W + ks * 8 + tg + 4]);
                    bll[0] = __float_as_uint(Ks_lo[(nt * 8 + g) * KS_W + ks * 8 + tg]);
                    bll[1] = __float_as_uint(Ks_lo[(nt * 8 + g) * KS_W + ks * 8 + tg + 4]);
                    mma_tf32(sc[nt], qa_hi[ks], bhh);
                    mma_tf32(sc[nt], qa_hi[ks], bll);
                    mma_tf32(sc[nt], qa_lo[ks], bhh);
                }
            }

            unsigned bw_g = g_bern[(bh * SQ + qrow_g) * 32u + (kb >> 5)];
            unsigned bw_h = g_bern[(bh * SQ + qrow_h) * 32u + (kb >> 5)];
            unsigned mw = msk[kb >> 5];

            float vals[4][4];
#pragma unroll
            for (int nt = 0; nt < 4; nt++) {
                int c0 = nt * 8 + tg * 2, c1 = c0 + 1;
                float v00 = sc[nt][0] * 0.125f + ps[(qrow_base + g) * PS_W + c0];
                float v01 = sc[nt][1] * 0.125f + ps[(qrow_base + g) * PS_W + c1];
                float v10 = sc[nt][2] * 0.125f + ps[(qrow_base + g + 8) * PS_W + c0];
                float v11 = sc[nt][3] * 0.125f + ps[(qrow_base + g + 8) * PS_W + c1];
                if ((bw_g >> c0) & 1u) v00 += -1e9f;
                if ((bw_g >> c1) & 1u) v01 += -1e9f;
                if ((bw_h >> c0) & 1u) v10 += -1e9f;
                if ((bw_h >> c1) & 1u) v11 += -1e9f;
                int kg0 = kb + c0, kg1 = kb + c1;
                if (((mw >> c0) & 1u) | (unsigned)(kg0 > qrow_g)) v00 = -1e9f;
                if (((mw >> c1) & 1u) | (unsigned)(kg1 > qrow_g)) v01 = -1e9f;
                if (((mw >> c0) & 1u) | (unsigned)(kg0 > qrow_h)) v10 = -1e9f;
                if (((mw >> c1) & 1u) | (unsigned)(kg1 > qrow_h)) v11 = -1e9f;
                vals[nt][0] = v00; vals[nt][1] = v01;
                vals[nt][2] = v10; vals[nt][3] = v11;
            }

            float rmax_g = vals[0][0], rmax_h = vals[0][2];
#pragma unroll
            for (int nt = 0; nt < 4; nt++) {
                rmax_g = fmaxf(rmax_g, fmaxf(vals[nt][0], vals[nt][1]));
                rmax_h = fmaxf(rmax_h, fmaxf(vals[nt][2], vals[nt][3]));
            }
            rmax_g = fmaxf(rmax_g, __shfl_xor_sync(0xffffffffu, rmax_g, 1));
            rmax_g = fmaxf(rmax_g, __shfl_xor_sync(0xffffffffu, rmax_g, 2));
            rmax_h = fmaxf(rmax_h, __shfl_xor_sync(0xffffffffu, rmax_h, 1));
            rmax_h = fmaxf(rmax_h, __shfl_xor_sync(0xffffffffu, rmax_h, 2));

            float mn_g = fmaxf(m_g, rmax_g);
            float mn_h = fmaxf(m_h, rmax_h);
            float corr_g = __expf(m_g - mn_g);
            float corr_h = __expf(m_h - mn_h);
            m_g = mn_g; m_h = mn_h;
            l_g *= corr_g; l_h *= corr_h;
#pragma unroll
            for (int nt = 0; nt < 8; nt++) {
                o[nt][0] *= corr_g; o[nt][1] *= corr_g;
                o[nt][2] *= corr_h; o[nt][3] *= corr_h;
            }

            float psum_g = 0.f, psum_h = 0.f;
#pragma unroll
            for (int nt = 0; nt < 4; nt++) {
                int c0 = nt * 8 + tg * 2;
                float p00 = __expf(vals[nt][0] - m_g);
                float p01 = __expf(vals[nt][1] - m_g);
                float p10 = __expf(vals[nt][2] - m_h);
                float p11 = __expf(vals[nt][3] - m_h);
                psum_g += p00 + p01;
                psum_h += p10 + p11;
                *(float2*)&Pt[g * PT_W + c0] = make_float2(p00, p01);
                *(float2*)&Pt[(g + 8) * PT_W + c0] = make_float2(p10, p11);
            }
            psum_g += __shfl_xor_sync(0xffffffffu, psum_g, 1);
            psum_g += __shfl_xor_sync(0xffffffffu, psum_g, 2);
            psum_h += __shfl_xor_sync(0xffffffffu, psum_h, 1);
            psum_h += __shfl_xor_sync(0xffffffffu, psum_h, 2);
            l_g += psum_g; l_h += psum_h;

            __syncwarp();

#pragma unroll
            for (int ks = 0; ks < 4; ks++) {
                float p0 = Pt[g * PT_W + ks * 8 + tg];
                float p1 = Pt[(g + 8) * PT_W + ks * 8 + tg];
                float p2 = Pt[g * PT_W + ks * 8 + tg + 4];
                float p3 = Pt[(g + 8) * PT_W + ks * 8 + tg + 4];
                unsigned pa_hi[4], pa_lo[4];
                pa_hi[0] = f2tf(p0); pa_lo[0] = f2tf(p0 - __uint_as_float(pa_hi[0]));
                pa_hi[1] = f2tf(p1); pa_lo[1] = f2tf(p1 - __uint_as_float(pa_hi[1]));
                pa_hi[2] = f2tf(p2); pa_lo[2] = f2tf(p2 - __uint_as_float(pa_hi[2]));
                pa_hi[3] = f2tf(p3); pa_lo[3] = f2tf(p3 - __uint_as_float(pa_hi[3]));
#pragma unroll
                for (int nt = 0; nt < 8; nt++) {
                    unsigned bhh[2], bll[2];
                    bhh[0] = __float_as_uint(Vs_hi[(ks * 8 + tg) * VS_W + nt * 8 + g]);
                    bhh[1] = __float_as_uint(Vs_hi[(ks * 8 + tg + 4) * VS_W + nt * 8 + g]);
                    bll[0] = __float_as_uint(Vs_lo[(ks * 8 + tg) * VS_W + nt * 8 + g]);
                    bll[1] = __float_as_uint(Vs_lo[(ks * 8 + tg + 4) * VS_W + nt * 8 + g]);
                    mma_tf32(o[nt], pa_hi, bhh);
                    mma_tf32(o[nt], pa_hi, bll);
                    mma_tf32(o[nt], pa_lo, bhh);
                }
            }
            __syncwarp();
        }
        sbuf ^= 1;
    }

    int jt = (qrow_g >> 5) + 1;
    if (jt < 32) {
        float pt_g = __expf(-1e9f - m_g);
        float pt_h = __expf(-1e9f - m_h);
        l_g += pt_g * (float)(1024 - jt * 32);
        l_h += pt_h * (float)(1024 - jt * 32);
        const float* sp = g_vsuf + (bh * 32 + jt) * 64;
#pragma unroll
        for (int nt = 0; nt < 8; nt++) {
            int c0 = nt * 8 + tg * 2;
            float s0 = sp[c0], s1 = sp[c0 + 1];
            o[nt][0] = fmaf(pt_g, s0, o[nt][0]);
            o[nt][1] = fmaf(pt_g, s1, o[nt][1]);
            o[nt][2] = fmaf(pt_h, s0, o[nt][2]);
            o[nt][3] = fmaf(pt_h, s1, o[nt][3]);
        }
    }

    // epilogue: write attention output fragment-packed for the out GEMM.
    // Pair (col, col+4) lives on lanes (tg, tg+2): exchange via shfl_xor 2.
    float ig = 1.0f / l_g, ih = 1.0f / l_h;
    int mg = b * 1024 + qrow_g;
    int mh = b * 1024 + qrow_h;
    float4* aop = (float4*)g_aop;
#pragma unroll
    for (int nt = 0; nt < 8; nt++) {
        float a0 = o[nt][0] * ig, a1 = o[nt][1] * ig;
        float a2 = o[nt][2] * ih, a3 = o[nt][3] * ih;
        float h0 = tf_hi(a0), l0 = tf_hi(a0 - h0);
        float h1 = tf_hi(a1), l1 = tf_hi(a1 - h1);
        float h2 = tf_hi(a2), l2 = tf_hi(a2 - h2);
        float h3 = tf_hi(a3), l3 = tf_hi(a3 - h3);
        float ph0 = __shfl_xor_sync(0xffffffffu, h0, 2);
        float pl0 = __shfl_xor_sync(0xffffffffu, l0, 2);
        float ph1 = __shfl_xor_sync(0xffffffffu, h1, 2);
        float pl1 = __shfl_xor_sync(0xffffffffu, l1, 2);
        float ph2 = __shfl_xor_sync(0xffffffffu, h2, 2);
        float pl2 = __shfl_xor_sync(0xffffffffu, l2, 2);
        float ph3 = __shfl_xor_sync(0xffffffffu, h3, 2);
        float pl3 = __shfl_xor_sync(0xffffffffu, l3, 2);
        if (tg < 2) {
            int colbase = h * 64 + nt * 8 + tg * 2;
            int pr0 = ((colbase >> 3) << 2) | (colbase & 3);
            aop[(size_t)pr0 * 4096 + mg]       = make_float4(h0, ph0, l0, pl0);
            aop[(size_t)(pr0 + 1) * 4096 + mg] = make_float4(h1, ph1, l1, pl1);
            aop[(size_t)pr0 * 4096 + mh]       = make_float4(h2, ph2, l2, pl2);
            aop[(size_t)(pr0 + 1) * 4096 + mh] = make_float4(h3, ph3, l3, pl3);
        }
    }
}

// ---------------- launch ----------------------------------------------------
extern "C" void kernel_launch(void* const* d_in, const int* in_sizes, int n_in,
                              void* d_out, int out_size) {
    (void)in_sizes; (void)n_in; (void)out_size;
    const float* x    = (const float*)d_in[0];
    const int*   mask = (const int*)d_in[1];
    const float* pos  = (const float*)d_in[2];
    const float* Wq = (const float*)d_in[4];
    const float* bq = (const float*)d_in[5];
    const float* Wk = (const float*)d_in[6];
    const float* bk = (const float*)d_in[7];
    const float* Wv = (const float*)d_in[8];
    const float* bv = (const float*)d_in[9];
    const float* Wo = (const float*)d_in[10];
    const float* bo = (const float*)d_in[11];
    float* out = (float*)d_out;

    static int smem_set = 0;
    if (!smem_set) {
        cudaFuncSetAttribute(qkv_gemm_kernel,
            cudaFuncAttributeMaxDynamicSharedMemorySize, SMEM_GEMM_BYTES);
        cudaFuncSetAttribute(out_gemm_kernel,
            cudaFuncAttributeMaxDynamicSharedMemorySize, SMEM_GEMM_BYTES);
        cudaFuncSetAttribute(attn_kernel,
            cudaFuncAttributeMaxDynamicSharedMemorySize, SMEM_ATTN_BYTES);
        smem_set = 1;
    }

    // fragment-pack x + all W (tf32 hi/lo quads)
    split_kernel<<<24576, 256>>>(x, Wq, Wk, Wv, Wo);

    // z=0..2: Q/K/V projections; z=3: bernoulli bits (overlapped)
    dim3 gg(8, 32, 4);
    qkv_gemm_kernel<<<gg, 256, SMEM_GEMM_BYTES>>>(bq, bk, bv);

    vsuf_kernel<<<64, 1024>>>();

    dim3 ga(8, NH, NB);
    attn_kernel<<<ga, 256, SMEM_ATTN_BYTES>>>(pos, mask);

    dim3 go(8, 32, 1);
    out_gemm_kernel<<<go, 256, SMEM_GEMM_BYTES>>>(bo, out);
}

// round 17
// speedup vs baseline: 1.0395x; 1.0395x over previous
#include <cuda_runtime.h>
#include <math.h>

#define NB 4
#define SQ 1024
#define DM 1024
#define NH 16
#define DKH 64
#define NKV (NB * NH * SQ * DKH)
#define NELEM 67108864u

// ---------------- scratch ----------------------------------------------------
__device__ unsigned g_bern[NELEM / 32];
__device__ float g_vsuf[64 * 32 * 64];
// pre-split tf32 hi/lo A-side operands
__device__ float g_xhi[4194304],  g_xlo[4194304];     // x [4096,1024]
__device__ float g_aohi[4194304], g_aolo[4194304];    // attn out [b,q,h,d]
// fragment-packed W: per W [pr=512][n=1024] float4 {hi[r],hi[r+4],lo[r],lo[r+4]}
__device__ float g_wp[8388608];
// attention operands (pre-split hi/lo, [b,h,s,d])
__device__ float g_qhi[NKV], g_qlo[NKV];
__device__ float g_khi[NKV], g_klo[NKV];
__device__ float g_vhi[NKV], g_vlo[NKV];

// ---------------- threefry2x32 (JAX partitionable, key=(0,42)) --------------
__device__ __forceinline__ unsigned rotl32(unsigned x, int r) {
    return __funnelshift_l(x, x, r);
}

__device__ __forceinline__ unsigned bern_bit(unsigned e) {
    unsigned x0 = 0u;
    unsigned x1 = e;
    const unsigned ks1 = 42u;
    const unsigned ks2 = 0x1BD11BDAu ^ 42u;
    x1 += ks1;
#define TF_RND(r) { x0 += x1; x1 = rotl32(x1, (r)); x1 ^= x0; }
    TF_RND(13) TF_RND(15) TF_RND(26) TF_RND(6)
    x0 += ks1; x1 += ks2 + 1u;
    TF_RND(17) TF_RND(29) TF_RND(16) TF_RND(24)
    x0 += ks2; x1 += 0u + 2u;
    TF_RND(13) TF_RND(15) TF_RND(26) TF_RND(6)
    x0 += 0u; x1 += ks1 + 3u;
    TF_RND(17) TF_RND(29) TF_RND(16) TF_RND(24)
    x0 += ks1; x1 += ks2 + 4u;
    TF_RND(13) TF_RND(15) TF_RND(26) TF_RND(6)
    x0 += ks2; x1 += 0u + 5u;
#undef TF_RND
    unsigned bits = x0 ^ x1;
    return ((bits >> 9) < 2516583u) ? 1u : 0u;   // uniform(bits) < 0.3f
}

__device__ void bern_chunk(int blk, int tid) {
    unsigned t = (unsigned)blk * 256u + (unsigned)tid;
    for (unsigned i = 0; i < 1024u; i++) {
        unsigned e = t + i * 65536u;
        unsigned qr = (e >> 10) & 1023u;
        unsigned kg0 = e & 992u;
        if (kg0 > qr) continue;           // dead bits (causal overwrite)
        unsigned keep = bern_bit(e);
        unsigned w = __ballot_sync(0xffffffffu, keep != 0u);
        if ((tid & 31) == 0) g_bern[e >> 5] = w;
    }
}

// ---------------- tf32 helpers ----------------------------------------------
__device__ __forceinline__ unsigned f2tf(float x) {
    unsigned r;
    asm("cvt.rna.tf32.f32 %0, %1;" : "=r"(r) : "f"(x));
    return r;
}
__device__ __forceinline__ float tf_hi(float x) { return __uint_as_float(f2tf(x)); }

__device__ __forceinline__ void mma_tf32(float c[4], const unsigned a[4], const unsigned b[2]) {
    asm volatile(
        "mma.sync.aligned.m16n8k8.row.col.f32.tf32.tf32.f32 "
        "{%0,%1,%2,%3}, {%4,%5,%6,%7}, {%8,%9}, {%0,%1,%2,%3};"
        : "+f"(c[0]), "+f"(c[1]), "+f"(c[2]), "+f"(c[3])
        : "r"(a[0]), "r"(a[1]), "r"(a[2]), "r"(a[3]), "r"(b[0]), "r"(b[1]));
}

__device__ __forceinline__ void cp16(void* dst_smem, const void* src) {
    unsigned d = (unsigned)__cvta_generic_to_shared(dst_smem);
    asm volatile("cp.async.cg.shared.global [%0], [%1], 16;" :: "r"(d), "l"(src) : "memory");
}

// ---------------- prep: x -> hi/lo (coalesced), W -> packed quads ------------
__global__ void __launch_bounds__(256) split_kernel(
    const float* __restrict__ x,
    const float* __restrict__ Wq, const float* __restrict__ Wk,
    const float* __restrict__ Wv, const float* __restrict__ Wo)
{
    unsigned idx = blockIdx.x * 256u + threadIdx.x;
    if (idx < 1048576u) {
        // x: one float4 per thread, hi/lo split, fully coalesced
        float4 v = ((const float4*)x)[idx];
        float4 h, l;
        h.x = tf_hi(v.x); l.x = tf_hi(v.x - h.x);
        h.y = tf_hi(v.y); l.y = tf_hi(v.y - h.y);
        h.z = tf_hi(v.z); l.z = tf_hi(v.z - h.z);
        h.w = tf_hi(v.w); l.w = tf_hi(v.w - h.w);
        ((float4*)g_xhi)[idx] = h;
        ((float4*)g_xlo)[idx] = l;
    } else {
        // W: packed quad per thread; reads & writes coalesced along n
        unsigned j = idx - 1048576u;      // 0 .. 2M-1
        unsigned w = j >> 19;             // 0..3
        unsigned rem = j & 524287u;       // pr*1024 + n
        unsigned pr = rem >> 10;
        unsigned n = rem & 1023u;
        unsigned r = (pr >> 2) * 8u + (pr & 3u);
        const float* W = (w == 0) ? Wq : (w == 1) ? Wk : (w == 2) ? Wv : Wo;
        float v0 = W[r * 1024 + n];
        float v1 = W[(r + 4) * 1024 + n];
        float h0 = tf_hi(v0), l0 = tf_hi(v0 - h0);
        float h1 = tf_hi(v1), l1 = tf_hi(v1 - h1);
        ((float4*)g_wp)[((size_t)w << 19) + rem] = make_float4(h0, h1, l0, l1);
    }
}

// ---------------- tf32x3 GEMM: hi/lo A + packed B ----------------------------
// BM=128, BN=128, BK=16; 8 warps 4(M)x2(N), warp tile 32x64; 3-stage cp.async.
#define AS_W 20
#define A_HSTAGE (128 * AS_W)          // 2560 floats per hi (or lo) A tile
#define FPAD 130                       // B float4 row stride (conflict-free)
#define B_STG4 (8 * FPAD)              // 1040 float4
#define STAGE_FLOATS (2 * A_HSTAGE + B_STG4 * 4)   // 9280
#define NSTAGE 3
#define SMEM_GEMM_BYTES (STAGE_FLOATS * NSTAGE * 4)  // 111360

__device__ __forceinline__ void issue_stage(
    const float* __restrict__ Ahi, const float* __restrict__ Alo,
    const float4* __restrict__ Bp,
    int m0, int n0, int kt, float* stage, int tid)
{
    float* sAh = stage;
    float* sAl = stage + A_HSTAGE;
    float4* sB = (float4*)(stage + 2 * A_HSTAGE);
#pragma unroll
    for (int i = 0; i < 2; i++) {
        int c = tid + i * 256;
        int m = c >> 2, kq = c & 3;
        size_t go = (size_t)(m0 + m) * 1024 + kt + kq * 4;
        int so = m * AS_W + kq * 4;
        cp16(sAh + so, Ahi + go);
        cp16(sAl + so, Alo + go);
    }
    {
        int kg0 = (kt >> 3) << 2;
#pragma unroll
        for (int i = 0; i < 4; i++) {
            int c = tid + i * 256;
            int rr = c >> 7, nn = c & 127;
            cp16(sB + rr * FPAD + nn, Bp + (size_t)(kg0 + rr) * 1024 + n0 + nn);
        }
    }
    asm volatile("cp.async.commit_group;" ::: "memory");
}

// SCATTER=1: write hi/lo float2 pairs in [b,h,s,d]; SCATTER=0: row-major out.
template <int SCATTER>
__device__ __forceinline__ void gemm_body(
    const float* __restrict__ Ahi, const float* __restrict__ Alo,
    const float4* __restrict__ Bp,
    const float* __restrict__ bias,
    float* __restrict__ outhi, float* __restrict__ outlo)
{
    extern __shared__ float sm[];
    int tid = threadIdx.x;
    int lane = tid & 31, warp = tid >> 5;
    int wm = warp & 3, wn = warp >> 2;
    int g = lane >> 2, tg = lane & 3;
    int m0 = blockIdx.y * 128, n0 = blockIdx.x * 128;

    float c[2][8][4];
#pragma unroll
    for (int mt = 0; mt < 2; mt++)
#pragma unroll
        for (int nt = 0; nt < 8; nt++)
#pragma unroll
            for (int i = 0; i < 4; i++) c[mt][nt][i] = 0.f;

    issue_stage(Ahi, Alo, Bp, m0, n0, 0, sm, tid);
    issue_stage(Ahi, Alo, Bp, m0, n0, 16, sm + STAGE_FLOATS, tid);

    int buf = 0;
    for (int it = 0; it < 64; it++) {
        if (it < 62) { asm volatile("cp.async.wait_group 1;" ::: "memory"); }
        else         { asm volatile("cp.async.wait_group 0;" ::: "memory"); }
        __syncthreads();

        if (it + 2 < 64) {
            int nbuf = buf + 2; if (nbuf >= NSTAGE) nbuf -= NSTAGE;
            issue_stage(Ahi, Alo, Bp, m0, n0, (it + 2) * 16,
                        sm + nbuf * STAGE_FLOATS, tid);
        }

        const float* sAh = sm + buf * STAGE_FLOATS;
        const float* sAl = sAh + A_HSTAGE;
        const float4* sB = (const float4*)(sAh + 2 * A_HSTAGE);

#pragma unroll
        for (int k8x = 0; k8x < 2; k8x++) {
            int k8 = k8x * 8;
            unsigned ah[2][4], al[2][4];
#pragma unroll
            for (int mt = 0; mt < 2; mt++) {
                int mb = wm * 32 + mt * 16;
                ah[mt][0] = __float_as_uint(sAh[(mb + g) * AS_W + k8 + tg]);
                ah[mt][1] = __float_as_uint(sAh[(mb + g + 8) * AS_W + k8 + tg]);
                ah[mt][2] = __float_as_uint(sAh[(mb + g) * AS_W + k8 + tg + 4]);
                ah[mt][3] = __float_as_uint(sAh[(mb + g + 8) * AS_W + k8 + tg + 4]);
                al[mt][0] = __float_as_uint(sAl[(mb + g) * AS_W + k8 + tg]);
                al[mt][1] = __float_as_uint(sAl[(mb + g + 8) * AS_W + k8 + tg]);
                al[mt][2] = __float_as_uint(sAl[(mb + g) * AS_W + k8 + tg + 4]);
                al[mt][3] = __float_as_uint(sAl[(mb + g + 8) * AS_W + k8 + tg + 4]);
            }
            int rowb = (k8x * 4 + tg) * FPAD;
#pragma unroll
            for (int nt = 0; nt < 8; nt++) {
                int nb = wn * 64 + nt * 8;
                float4 Bv = sB[rowb + nb + g];
                unsigned bh[2], bl[2];
                bh[0] = __float_as_uint(Bv.x); bh[1] = __float_as_uint(Bv.y);
                bl[0] = __float_as_uint(Bv.z); bl[1] = __float_as_uint(Bv.w);
#pragma unroll
                for (int mt = 0; mt < 2; mt++) {
                    mma_tf32(c[mt][nt], ah[mt], bh);
                    mma_tf32(c[mt][nt], ah[mt], bl);
                    mma_tf32(c[mt][nt], al[mt], bh);
                }
            }
        }
        buf++; if (buf >= NSTAGE) buf = 0;
    }

#pragma unroll
    for (int mt = 0; mt < 2; mt++)
#pragma unroll
        for (int nt = 0; nt < 8; nt++)
#pragma unroll
            for (int half = 0; half < 2; half++) {
                int row = m0 + wm * 32 + mt * 16 + g + half * 8;
                int col0 = n0 + wn * 64 + nt * 8 + tg * 2;
                float v0 = fmaxf(c[mt][nt][half * 2 + 0] + bias[col0], 0.f);
                float v1 = fmaxf(c[mt][nt][half * 2 + 1] + bias[col0 + 1], 0.f);
                if (SCATTER) {
                    int b = row >> 10, s = row & 1023;
                    int h = col0 >> 6, d = col0 & 63;
                    size_t idx = (((size_t)(b * NH + h)) * SQ + s) * DKH + d;
                    float h0 = tf_hi(v0);
                    float h1 = tf_hi(v1);
                    *(float2*)(outhi + idx) = make_float2(h0, h1);
                    *(float2*)(outlo + idx) = make_float2(tf_hi(v0 - h0), tf_hi(v1 - h1));
                } else {
                    *(float2*)(outhi + (size_t)row * 1024 + col0) = make_float2(v0, v1);
                }
            }
}

// z = 0/1/2: q/k/v projections. z = 3: bernoulli slice.
__global__ void __launch_bounds__(256, 2) qkv_gemm_kernel(
    const float* __restrict__ bq, const float* __restrict__ bk,
    const float* __restrict__ bv)
{
    if (blockIdx.z == 3) {
        bern_chunk(blockIdx.y * 8 + blockIdx.x, threadIdx.x);
        return;
    }
    int proj = blockIdx.z;
    const float* bias = (proj == 0) ? bq : (proj == 1) ? bk : bv;
    float* ohi = (proj == 0) ? g_qhi : (proj == 1) ? g_khi : g_vhi;
    float* olo = (proj == 0) ? g_qlo : (proj == 1) ? g_klo : g_vlo;
    gemm_body<1>(g_xhi, g_xlo,
                 (const float4*)g_wp + ((size_t)proj << 19),
                 bias, ohi, olo);
}

__global__ void __launch_bounds__(256, 2) out_gemm_kernel(
    const float* __restrict__ bias, float* __restrict__ out)
{
    gemm_body<0>(g_aohi, g_aolo,
                 (const float4*)g_wp + ((size_t)3 << 19),
                 bias, out, (float*)0);
}

// ---------------- V suffix sums (from hi+lo; error ~2^-22, negligible) -------
__global__ void __launch_bounds__(1024) vsuf_kernel() {
    int bh = blockIdx.x;
    __shared__ float part[32][64];
    int d = threadIdx.x & 63;
    int jj = threadIdx.x >> 6;
#pragma unroll
    for (int p = 0; p < 2; p++) {
        int j = p * 16 + jj;
        size_t base = ((size_t)bh * 1024 + j * 32) * 64 + d;
        float sum = 0.f;
#pragma unroll
        for (int s = 0; s < 32; s++)
            sum += g_vhi[base + s * 64] + g_vlo[base + s * 64];
        part[j][d] = sum;
    }
    __syncthreads();
    if (threadIdx.x < 64) {
        float run = 0.f;
        for (int j = 31; j >= 0; j--) {
            run += part[j][threadIdx.x];
            g_vsuf[((size_t)bh * 32 + j) * 64 + threadIdx.x] = run;
        }
    }
}

// ---------------- MMA flash attention: pre-split + cp.async double buffer ----
#define KS_W 76
#define VS_W 72
#define PS_W 36
#define PT_W 36
#define KOFF (32 * KS_W)
#define VOFF (32 * VS_W)
#define PSOFF (2 * KOFF + 2 * VOFF)
#define ATT_STAGE (PSOFF + 128 * PS_W)
#define SMEM_ATTN_FLOATS (2 * ATT_STAGE + 8 * 16 * PT_W + 32)
#define SMEM_ATTN_BYTES (SMEM_ATTN_FLOATS * 4)   // 131200

__device__ __forceinline__ void attn_issue(
    float* st, size_t kvbase, const float* __restrict__ pos,
    size_t posbase, int kb, int tid)
{
    float* Kh = st;
    float* Kl = st + KOFF;
    float* Vh = st + 2 * KOFF;
    float* Vl = st + 2 * KOFF + VOFF;
    float* ps = st + PSOFF;
#pragma unroll
    for (int i = 0; i < 2; i++) {
        int c = tid + i * 256;
        int key = c >> 4, d4 = (c & 15) * 4;
        size_t go = kvbase + key * 64 + d4;
        cp16(Kh + key * KS_W + d4, g_khi + go);
        cp16(Kl + key * KS_W + d4, g_klo + go);
        cp16(Vh + key * VS_W + d4, g_vhi + go);
        cp16(Vl + key * VS_W + d4, g_vlo + go);
    }
#pragma unroll
    for (int i = 0; i < 4; i++) {
        int c = tid + i * 256;
        int r = c >> 3, c4 = (c & 7) * 4;
        cp16(ps + r * PS_W + c4, pos + posbase + (size_t)r * SQ + kb + c4);
    }
    asm volatile("cp.async.commit_group;" ::: "memory");
}

__global__ void __launch_bounds__(256) attn_kernel(
    const float* __restrict__ pos, const int* __restrict__ mask)
{
    extern __shared__ float sm[];
    float* PtAll = sm + 2 * ATT_STAGE;
    unsigned* msk = (unsigned*)(PtAll + 8 * 16 * PT_W);   // [32] packed pad-mask

    int qb = (int)gridDim.x - 1 - (int)blockIdx.x;   // heavy blocks first
    int h = blockIdx.y, b = blockIdx.z;
    int tid = threadIdx.x;
    int lane = tid & 31, warp = tid >> 5;
    int g = lane >> 2, tg = lane & 3;
    float* Pt = PtAll + warp * 16 * PT_W;

    int qr0 = qb * 128 + warp * 16;
    int qrow_g = qr0 + g;
    int qrow_h = qr0 + g + 8;
    size_t bh = (size_t)(b * NH + h);
    size_t posbase = ((size_t)b * SQ + qb * 128) * SQ;

    // Pack the key-padding mask once per block: 32 words, 4 per warp.
#pragma unroll
    for (int j = 0; j < 4; j++) {
        int w = warp * 4 + j;
        unsigned bit = (mask[b * SQ + w * 32 + lane] != 0) ? 1u : 0u;
        unsigned word = __ballot_sync(0xffffffffu, bit != 0u);
        if (lane == 0) msk[w] = word;
    }

    // Q fragments: pre-split, straight into registers
    unsigned qa_hi[8][4], qa_lo[8][4];
    {
        const float* qh = g_qhi + (bh * SQ + qr0) * DKH;
        const float* ql = g_qlo + (bh * SQ + qr0) * DKH;
#pragma unroll
        for (int ks = 0; ks < 8; ks++) {
            qa_hi[ks][0] = __float_as_uint(qh[g * 64 + ks * 8 + tg]);
            qa_hi[ks][1] = __float_as_uint(qh[(g + 8) * 64 + ks * 8 + tg]);
            qa_hi[ks][2] = __float_as_uint(qh[g * 64 + ks * 8 + tg + 4]);
            qa_hi[ks][3] = __float_as_uint(qh[(g + 8) * 64 + ks * 8 + tg + 4]);
            qa_lo[ks][0] = __float_as_uint(ql[g * 64 + ks * 8 + tg]);
            qa_lo[ks][1] = __float_as_uint(ql[(g + 8) * 64 + ks * 8 + tg]);
            qa_lo[ks][2] = __float_as_uint(ql[g * 64 + ks * 8 + tg + 4]);
            qa_lo[ks][3] = __float_as_uint(ql[(g + 8) * 64 + ks * 8 + tg + 4]);
        }
    }

    float o[8][4];
#pragma unroll
    for (int nt = 0; nt < 8; nt++)
#pragma unroll
        for (int i = 0; i < 4; i++) o[nt][i] = 0.f;
    float m_g = -INFINITY, m_h = -INFINITY, l_g = 0.f, l_h = 0.f;

    int kb_end = (qb + 1) * 128;
    int qrow_base = warp * 16;

    attn_issue(sm, (bh * SQ + 0) * DKH, pos, posbase, 0, tid);

    int sbuf = 0;
    for (int kb = 0; kb < kb_end; kb += 32) {
        asm volatile("cp.async.wait_group 0;" ::: "memory");
        __syncthreads();
        if (kb + 32 < kb_end)
            attn_issue(sm + (sbuf ^ 1) * ATT_STAGE,
                       (bh * SQ + kb + 32) * DKH, pos, posbase, kb + 32, tid);

        const float* st = sm + sbuf * ATT_STAGE;
        const float* Ks_hi = st;
        const float* Ks_lo = st + KOFF;
        const float* Vs_hi = st + 2 * KOFF;
        const float* Vs_lo = st + 2 * KOFF + VOFF;
        const float* ps    = st + PSOFF;

        if (kb <= qr0) {
            float sc[4][4];
#pragma unroll
            for (int nt = 0; nt < 4; nt++)
#pragma unroll
                for (int i = 0; i < 4; i++) sc[nt][i] = 0.f;
#pragma unroll
            for (int ks = 0; ks < 8; ks++) {
#pragma unroll
                for (int nt = 0; nt < 4; nt++) {
                    unsigned bhh[2], bll[2];
                    bhh[0] = __float_as_uint(Ks_hi[(nt * 8 + g) * KS_W + ks * 8 + tg]);
                    bhh[1] = __float_as_uint(Ks_hi[(nt * 8 + g) * KS_W + ks * 8 + tg + 4]);
                    bll[0] = __float_as_uint(Ks_lo[(nt * 8 + g) * KS_W + ks * 8 + tg]);
                    bll[1] = __float_as_uint(Ks_lo[(nt * 8 + g) * KS_W + ks * 8 + tg + 4]);
                    mma_tf32(sc[nt], qa_hi[ks], bhh);
                    mma_tf32(sc[nt], qa_hi[ks], bll);
                    mma_tf32(sc[nt], qa_lo[ks], bhh);
                }
            }

            unsigned bw_g = g_bern[(bh * SQ + qrow_g) * 32u + (kb >> 5)];
            unsigned bw_h = g_bern[(bh * SQ + qrow_h) * 32u + (kb >> 5)];
            unsigned mw = msk[kb >> 5];

            float vals[4][4];
#pragma unroll
            for (int nt = 0; nt < 4; nt++) {
                int c0 = nt * 8 + tg * 2, c1 = c0 + 1;
                float v00 = sc[nt][0] * 0.125f + ps[(qrow_base + g) * PS_W + c0];
                float v01 = sc[nt][1] * 0.125f + ps[(qrow_base + g) * PS_W + c1];
                float v10 = sc[nt][2] * 0.125f + ps[(qrow_base + g + 8) * PS_W + c0];
                float v11 = sc[nt][3] * 0.125f + ps[(qrow_base + g + 8) * PS_W + c1];
                if ((bw_g >> c0) & 1u) v00 += -1e9f;
                if ((bw_g >> c1) & 1u) v01 += -1e9f;
                if ((bw_h >> c0) & 1u) v10 += -1e9f;
                if ((bw_h >> c1) & 1u) v11 += -1e9f;
                int kg0 = kb + c0, kg1 = kb + c1;
                if (((mw >> c0) & 1u) | (unsigned)(kg0 > qrow_g)) v00 = -1e9f;
                if (((mw >> c1) & 1u) | (unsigned)(kg1 > qrow_g)) v01 = -1e9f;
                if (((mw >> c0) & 1u) | (unsigned)(kg0 > qrow_h)) v10 = -1e9f;
                if (((mw >> c1) & 1u) | (unsigned)(kg1 > qrow_h)) v11 = -1e9f;
                vals[nt][0] = v00; vals[nt][1] = v01;
                vals[nt][2] = v10; vals[nt][3] = v11;
            }

            float rmax_g = vals[0][0], rmax_h = vals[0][2];
#pragma unroll
            for (int nt = 0; nt < 4; nt++) {
                rmax_g = fmaxf(rmax_g, fmaxf(vals[nt][0], vals[nt][1]));
                rmax_h = fmaxf(rmax_h, fmaxf(vals[nt][2], vals[nt][3]));
            }
            rmax_g = fmaxf(rmax_g, __shfl_xor_sync(0xffffffffu, rmax_g, 1));
            rmax_g = fmaxf(rmax_g, __shfl_xor_sync(0xffffffffu, rmax_g, 2));
            rmax_h = fmaxf(rmax_h, __shfl_xor_sync(0xffffffffu, rmax_h, 1));
            rmax_h = fmaxf(rmax_h, __shfl_xor_sync(0xffffffffu, rmax_h, 2));

            float mn_g = fmaxf(m_g, rmax_g);
            float mn_h = fmaxf(m_h, rmax_h);
            float corr_g = __expf(m_g - mn_g);
            float corr_h = __expf(m_h - mn_h);
            m_g = mn_g; m_h = mn_h;
            l_g *= corr_g; l_h *= corr_h;
#pragma unroll
            for (int nt = 0; nt < 8; nt++) {
                o[nt][0] *= corr_g; o[nt][1] *= corr_g;
                o[nt][2] *= corr_h; o[nt][3] *= corr_h;
            }

            float psum_g = 0.f, psum_h = 0.f;
#pragma unroll
            for (int nt = 0; nt < 4; nt++) {
                int c0 = nt * 8 + tg * 2;
                float p00 = __expf(vals[nt][0] - m_g);
                float p01 = __expf(vals[nt][1] - m_g);
                float p10 = __expf(vals[nt][2] - m_h);
                float p11 = __expf(vals[nt][3] - m_h);
                psum_g += p00 + p01;
                psum_h += p10 + p11;
                *(float2*)&Pt[g * PT_W + c0] = make_float2(p00, p01);
                *(float2*)&Pt[(g + 8) * PT_W + c0] = make_float2(p10, p11);
            }
            psum_g += __shfl_xor_sync(0xffffffffu, psum_g, 1);
            psum_g += __shfl_xor_sync(0xffffffffu, psum_g, 2);
            psum_h += __shfl_xor_sync(0xffffffffu, psum_h, 1);
            psum_h += __shfl_xor_sync(0xffffffffu, psum_h, 2);
            l_g += psum_g; l_h += psum_h;

            __syncwarp();

#pragma unroll
            for (int ks = 0; ks < 4; ks++) {
                float p0 = Pt[g * PT_W + ks * 8 + tg];
                float p1 = Pt[(g + 8) * PT_W + ks * 8 + tg];
                float p2 = Pt[g * PT_W + ks * 8 + tg + 4];
                float p3 = Pt[(g + 8) * PT_W + ks * 8 + tg + 4];
                unsigned pa_hi[4], pa_lo[4];
                pa_hi[0] = f2tf(p0); pa_lo[0] = f2tf(p0 - __uint_as_float(pa_hi[0]));
                pa_hi[1] = f2tf(p1); pa_lo[1] = f2tf(p1 - __uint_as_float(pa_hi[1]));
                pa_hi[2] = f2tf(p2); pa_lo[2] = f2tf(p2 - __uint_as_float(pa_hi[2]));
                pa_hi[3] = f2tf(p3); pa_lo[3] = f2tf(p3 - __uint_as_float(pa_hi[3]));
#pragma unroll
                for (int nt = 0; nt < 8; nt++) {
                    unsigned bhh[2], bll[2];
                    bhh[0] = __float_as_uint(Vs_hi[(ks * 8 + tg) * VS_W + nt * 8 + g]);
                    bhh[1] = __float_as_uint(Vs_hi[(ks * 8 + tg + 4) * VS_W + nt * 8 + g]);
                    bll[0] = __float_as_uint(Vs_lo[(ks * 8 + tg) * VS_W + nt * 8 + g]);
                    bll[1] = __float_as_uint(Vs_lo[(ks * 8 + tg + 4) * VS_W + nt * 8 + g]);
                    mma_tf32(o[nt], pa_hi, bhh);
                    mma_tf32(o[nt], pa_hi, bll);
                    mma_tf32(o[nt], pa_lo, bhh);
                }
            }
            __syncwarp();
        }
        sbuf ^= 1;
    }

    int jt = (qrow_g >> 5) + 1;
    if (jt < 32) {
        float pt_g = __expf(-1e9f - m_g);
        float pt_h = __expf(-1e9f - m_h);
        l_g += pt_g * (float)(1024 - jt * 32);
        l_h += pt_h * (float)(1024 - jt * 32);
        const float* sp = g_vsuf + (bh * 32 + jt) * 64;
#pragma unroll
        for (int nt = 0; nt < 8; nt++) {
            int c0 = nt * 8 + tg * 2;
            float s0 = sp[c0], s1 = sp[c0 + 1];
            o[nt][0] = fmaf(pt_g, s0, o[nt][0]);
            o[nt][1] = fmaf(pt_g, s1, o[nt][1]);
            o[nt][2] = fmaf(pt_h, s0, o[nt][2]);
            o[nt][3] = fmaf(pt_h, s1, o[nt][3]);
        }
    }

    // epilogue: write attention output pre-split (hi/lo) for the out GEMM
    float ig = 1.0f / l_g, ih = 1.0f / l_h;
    size_t og = (((size_t)b * SQ + qrow_g) * NH + h) * DKH;
    size_t oh = (((size_t)b * SQ + qrow_h) * NH + h) * DKH;
#pragma unroll
    for (int nt = 0; nt < 8; nt++) {
        int c0 = nt * 8 + tg * 2;
        float a0 = o[nt][0] * ig, a1 = o[nt][1] * ig;
        float a2 = o[nt][2] * ih, a3 = o[nt][3] * ih;
        float h0 = tf_hi(a0);
        float h1 = tf_hi(a1);
        float h2 = tf_hi(a2);
        float h3 = tf_hi(a3);
        *(float2*)(g_aohi + og + c0) = make_float2(h0, h1);
        *(float2*)(g_aohi + oh + c0) = make_float2(h2, h3);
        *(float2*)(g_aolo + og + c0) = make_float2(tf_hi(a0 - h0), tf_hi(a1 - h1));
        *(float2*)(g_aolo + oh + c0) = make_float2(tf_hi(a2 - h2), tf_hi(a3 - h3));
    }
}

// ---------------- launch ----------------------------------------------------
extern "C" void kernel_launch(void* const* d_in, const int* in_sizes, int n_in,
                              void* d_out, int out_size) {
    (void)in_sizes; (void)n_in; (void)out_size;
    const float* x    = (const float*)d_in[0];
    const int*   mask = (const int*)d_in[1];
    const float* pos  = (const float*)d_in[2];
    const float* Wq = (const float*)d_in[4];
    const float* bq = (const float*)d_in[5];
    const float* Wk = (const float*)d_in[6];
    const float* bk = (const float*)d_in[7];
    const float* Wv = (const float*)d_in[8];
    const float* bv = (const float*)d_in[9];
    const float* Wo = (const float*)d_in[10];
    const float* bo = (const float*)d_in[11];
    float* out = (float*)d_out;

    static int smem_set = 0;
    if (!smem_set) {
        cudaFuncSetAttribute(qkv_gemm_kernel,
            cudaFuncAttributeMaxDynamicSharedMemorySize, SMEM_GEMM_BYTES);
        cudaFuncSetAttribute(out_gemm_kernel,
            cudaFuncAttributeMaxDynamicSharedMemorySize, SMEM_GEMM_BYTES);
        cudaFuncSetAttribute(attn_kernel,
            cudaFuncAttributeMaxDynamicSharedMemorySize, SMEM_ATTN_BYTES);
        smem_set = 1;
    }

    // x -> hi/lo (coalesced), W -> packed fragment quads
    split_kernel<<<12288, 256>>>(x, Wq, Wk, Wv, Wo);

    // z=0..2: Q/K/V projections; z=3: bernoulli bits (overlapped)
    dim3 gg(8, 32, 4);
    qkv_gemm_kernel<<<gg, 256, SMEM_GEMM_BYTES>>>(bq, bk, bv);

    vsuf_kernel<<<64, 1024>>>();

    dim3 ga(8, NH, NB);
    attn_kernel<<<ga, 256, SMEM_ATTN_BYTES>>>(pos, mask);

    dim3 go(8, 32, 1);
    out_gemm_kernel<<<go, 256, SMEM_GEMM_BYTES>>>(bo, out);
}